// round 12
// baseline (speedup 1.0000x reference)
#include <cuda_runtime.h>
#include <cuda_bf16.h>
#include <stdint.h>

// Problem shape (fixed by the dataset):
//   N = 100000 nodes, E = 1200000 edges, D_IN = D_HID = 64
// out[n,:] = sum_{e: dst[e]==n} w[e] * data[src[e],:] @ theta
// Linearity => project first: proj = data @ theta  (N x 64),
// then out[dst[e]] += w[e] * proj[src[e]]  (scatter with vector red).

#define D 64
#define MAX_NODES 100096   // padded scratch capacity (N = 100000)

// Scratch for the projected node features (device global — no allocation).
__device__ float g_proj[(size_t)MAX_NODES * D];

// ---------------------------------------------------------------------------
// Kernel 1: proj[N,64] = data[N,64] @ theta[64,64]
// Block: 256 threads, tile = 64 rows x 64 cols, full K=64 staged in smem.
// Thread (ty=tid/16, tx=tid%16) computes a 4x4 register tile:
//   rows ty*4..ty*4+3, cols tx*4..tx*4+3.
// ---------------------------------------------------------------------------
__global__ __launch_bounds__(256)
void proj_kernel(const float* __restrict__ data,
                 const float* __restrict__ theta,
                 float* __restrict__ proj,
                 int N)
{
    __shared__ float sTheta[D * D];   // 16 KB, [k][c]
    __shared__ float sData[64 * D];   // 16 KB, [r][k]

    const int tid = threadIdx.x;
    const int rowBase = blockIdx.x * 64;

    // Load theta (row-major [k][c]) — 1024 float4, 4 per thread.
    {
        const float4* t4 = reinterpret_cast<const float4*>(theta);
        float4* st4 = reinterpret_cast<float4*>(sTheta);
        #pragma unroll
        for (int i = 0; i < 4; i++)
            st4[tid + i * 256] = t4[tid + i * 256];
    }

    // Load the 64x64 data tile (zero-fill out-of-range rows).
    {
        float4* sd4 = reinterpret_cast<float4*>(sData);
        const float4* g4 = reinterpret_cast<const float4*>(data);
        #pragma unroll
        for (int i = 0; i < 4; i++) {
            int idx = tid + i * 256;        // 0..1023 float4 within tile
            int r = idx >> 4;               // row within tile (16 float4 per row)
            int gr = rowBase + r;
            float4 v = make_float4(0.f, 0.f, 0.f, 0.f);
            if (gr < N) v = g4[(size_t)gr * (D / 4) + (idx & 15)];
            sd4[idx] = v;
        }
    }
    __syncthreads();

    const int ty = tid >> 4;   // 0..15  -> rows ty*4..+3
    const int tx = tid & 15;   // 0..15  -> cols tx*4..+3

    float acc[4][4];
    #pragma unroll
    for (int i = 0; i < 4; i++)
        #pragma unroll
        for (int j = 0; j < 4; j++)
            acc[i][j] = 0.f;

    #pragma unroll 8
    for (int k = 0; k < D; k++) {
        float4 b = *reinterpret_cast<const float4*>(&sTheta[k * D + tx * 4]);
        float a0 = sData[(ty * 4 + 0) * D + k];
        float a1 = sData[(ty * 4 + 1) * D + k];
        float a2 = sData[(ty * 4 + 2) * D + k];
        float a3 = sData[(ty * 4 + 3) * D + k];
        acc[0][0] += a0 * b.x; acc[0][1] += a0 * b.y; acc[0][2] += a0 * b.z; acc[0][3] += a0 * b.w;
        acc[1][0] += a1 * b.x; acc[1][1] += a1 * b.y; acc[1][2] += a1 * b.z; acc[1][3] += a1 * b.w;
        acc[2][0] += a2 * b.x; acc[2][1] += a2 * b.y; acc[2][2] += a2 * b.z; acc[2][3] += a2 * b.w;
        acc[3][0] += a3 * b.x; acc[3][1] += a3 * b.y; acc[3][2] += a3 * b.z; acc[3][3] += a3 * b.w;
    }

    #pragma unroll
    for (int i = 0; i < 4; i++) {
        int gr = rowBase + ty * 4 + i;
        if (gr < N) {
            float4 v = make_float4(acc[i][0], acc[i][1], acc[i][2], acc[i][3]);
            *reinterpret_cast<float4*>(&proj[(size_t)gr * D + tx * 4]) = v;
        }
    }
}

// ---------------------------------------------------------------------------
// Kernel 2: edge scatter.  16 threads per edge, one float4 lane-group each:
//   out[dst[e], part*4 .. part*4+3] += w[e] * proj[src[e], part*4 .. +3]
// Uses red.global.add.v4.f32 (sm_90+ vector reduction, no return) so the
// atomic count is E*16 = 19.2M instead of 76.8M scalars.
// ---------------------------------------------------------------------------
__global__ __launch_bounds__(256)
void scatter_kernel(const int* __restrict__ src,
                    const int* __restrict__ dst,
                    const float* __restrict__ w,
                    const float* __restrict__ proj,
                    float* __restrict__ out,
                    int E)
{
    int gid = blockIdx.x * blockDim.x + threadIdx.x;
    int e = gid >> 4;
    if (e >= E) return;
    int part = gid & 15;

    int s = src[e];                 // same addr for 16 lanes -> L1 broadcast
    int d = dst[e];
    float we = w[e];

    float4 v = reinterpret_cast<const float4*>(proj + (size_t)s * D)[part];
    v.x *= we; v.y *= we; v.z *= we; v.w *= we;

    float* o = out + (size_t)d * D + part * 4;
    asm volatile("red.global.add.v4.f32 [%0], {%1, %2, %3, %4};"
                 :: "l"(o), "f"(v.x), "f"(v.y), "f"(v.z), "f"(v.w)
                 : "memory");
}

// ---------------------------------------------------------------------------
// kernel_launch: memset(out) -> proj GEMM -> edge scatter. Graph-capturable:
// only async memset + kernel launches on the legacy stream, no allocation.
// Input order (metadata): src[E] i32, dst[E] i32, w[E] f32,
//                         data[N*64] f32, theta[64*64] f32, num_nodes i32
// ---------------------------------------------------------------------------
extern "C" void kernel_launch(void* const* d_in, const int* in_sizes, int n_in,
                              void* d_out, int out_size)
{
    const int*   src   = (const int*)  d_in[0];
    const int*   dst   = (const int*)  d_in[1];
    const float* w     = (const float*)d_in[2];
    const float* data  = (const float*)d_in[3];
    const float* theta = (const float*)d_in[4];

    const int E = in_sizes[0];
    const int N = in_sizes[3] / D;

    float* out = (float*)d_out;

    // Resolve scratch address (device symbol -> pointer, no allocation).
    static float* proj_ptr = nullptr;
    if (!proj_ptr) {
        void* p = nullptr;
        cudaGetSymbolAddress(&p, g_proj);
        proj_ptr = (float*)p;
    }

    // Zero the output accumulator (poisoned to 0xAA by the harness).
    cudaMemsetAsync(d_out, 0, (size_t)out_size * sizeof(float), 0);

    // proj = data @ theta
    int gemmBlocks = (N + 63) / 64;
    proj_kernel<<<gemmBlocks, 256>>>(data, theta, proj_ptr, N);

    // out[dst] += w * proj[src]
    long long totalThreads = (long long)E * 16;
    int scatterBlocks = (int)((totalThreads + 255) / 256);
    scatter_kernel<<<scatterBlocks, 256>>>(src, dst, w, proj_ptr, out, E);
}

// round 13
// speedup vs baseline: 1.2636x; 1.2636x over previous
#include <cuda_runtime.h>
#include <cuda_bf16.h>
#include <stdint.h>

// GCN: out[n,:] = sum_{e: dst[e]==n} w[e] * data[src[e],:] @ theta
// Linearity => project FIRST (proj = data@theta, 25.6MB, L2-resident),
// then aggregate. R12 change: replace the 19.2M-vector-atomic scatter with
// bucket-build + per-node gather-reduce (zero atomics in the hot path),
// and overlap the GEMM with the bucket build via a forked stream.
//
// Shapes (fixed): N = 100000 nodes, E = 1200000 edges, D = 64.

#define D 64
#define MAX_NODES 100096
#define CAP 64            // per-node bucket capacity; Poisson(12) max-degree ~40
#define OVF_CAP 32768     // overflow safety net (normally empty)

// Static device scratch (no runtime allocation).
__device__ float g_proj[(size_t)MAX_NODES * D];          // 25.6 MB
__device__ int2  g_bucket[(size_t)MAX_NODES * CAP];      // 51.2 MB: {src, w_bits}
__device__ int   g_cnt[MAX_NODES];
__device__ int   g_ovf_cnt;
__device__ int   g_ovf_list[OVF_CAP];

// ---------------------------------------------------------------------------
// Kernel 1: proj[N,64] = data[N,64] @ theta[64,64]
// 256 threads/block, 64x64 tile, 4x4 register tile per thread.
// ---------------------------------------------------------------------------
__global__ __launch_bounds__(256)
void proj_kernel(const float* __restrict__ data,
                 const float* __restrict__ theta,
                 float* __restrict__ proj,
                 int N)
{
    __shared__ float sTheta[D * D];   // [k][c]
    __shared__ float sData[64 * D];   // [r][k]

    const int tid = threadIdx.x;
    const int rowBase = blockIdx.x * 64;

    {
        const float4* t4 = reinterpret_cast<const float4*>(theta);
        float4* st4 = reinterpret_cast<float4*>(sTheta);
        #pragma unroll
        for (int i = 0; i < 4; i++)
            st4[tid + i * 256] = t4[tid + i * 256];
    }
    {
        float4* sd4 = reinterpret_cast<float4*>(sData);
        const float4* g4 = reinterpret_cast<const float4*>(data);
        #pragma unroll
        for (int i = 0; i < 4; i++) {
            int idx = tid + i * 256;
            int r = idx >> 4;
            int gr = rowBase + r;
            float4 v = make_float4(0.f, 0.f, 0.f, 0.f);
            if (gr < N) v = g4[(size_t)gr * (D / 4) + (idx & 15)];
            sd4[idx] = v;
        }
    }
    __syncthreads();

    const int ty = tid >> 4;
    const int tx = tid & 15;

    float acc[4][4];
    #pragma unroll
    for (int i = 0; i < 4; i++)
        #pragma unroll
        for (int j = 0; j < 4; j++)
            acc[i][j] = 0.f;

    #pragma unroll 8
    for (int k = 0; k < D; k++) {
        float4 b = *reinterpret_cast<const float4*>(&sTheta[k * D + tx * 4]);
        float a0 = sData[(ty * 4 + 0) * D + k];
        float a1 = sData[(ty * 4 + 1) * D + k];
        float a2 = sData[(ty * 4 + 2) * D + k];
        float a3 = sData[(ty * 4 + 3) * D + k];
        acc[0][0] += a0 * b.x; acc[0][1] += a0 * b.y; acc[0][2] += a0 * b.z; acc[0][3] += a0 * b.w;
        acc[1][0] += a1 * b.x; acc[1][1] += a1 * b.y; acc[1][2] += a1 * b.z; acc[1][3] += a1 * b.w;
        acc[2][0] += a2 * b.x; acc[2][1] += a2 * b.y; acc[2][2] += a2 * b.z; acc[2][3] += a2 * b.w;
        acc[3][0] += a3 * b.x; acc[3][1] += a3 * b.y; acc[3][2] += a3 * b.z; acc[3][3] += a3 * b.w;
    }

    #pragma unroll
    for (int i = 0; i < 4; i++) {
        int gr = rowBase + ty * 4 + i;
        if (gr < N) {
            float4 v = make_float4(acc[i][0], acc[i][1], acc[i][2], acc[i][3]);
            *reinterpret_cast<float4*>(&proj[(size_t)gr * D + tx * 4]) = v;
        }
    }
}

// ---------------------------------------------------------------------------
// Kernel 2: bucket build. One thread per edge:
//   pos = cnt[dst]++; bucket[dst*CAP+pos] = {src, w}
// Overflow (degree > CAP, ~impossible) goes to an overflow list handled by
// cleanup_kernel so correctness never depends on the CAP assumption.
// ---------------------------------------------------------------------------
__global__ __launch_bounds__(256)
void fill_kernel(const int* __restrict__ src, const int* __restrict__ dst,
                 const float* __restrict__ w, int E)
{
    int e = blockIdx.x * blockDim.x + threadIdx.x;
    if (e >= E) return;
    int d = dst[e];
    int pos = atomicAdd(&g_cnt[d], 1);
    if (pos < CAP) {
        g_bucket[((size_t)d << 6) + pos] = make_int2(src[e], __float_as_int(w[e]));
    } else {
        int op = atomicAdd(&g_ovf_cnt, 1);
        if (op < OVF_CAP) g_ovf_list[op] = e;
    }
}

// ---------------------------------------------------------------------------
// Kernel 3: gather-reduce. 16 lanes per node, each lane owns one float4
// column slice. Register accumulation, ONE coalesced float4 store per node
// (no atomics, no output memset needed).
// ---------------------------------------------------------------------------
__global__ __launch_bounds__(256)
void gather_kernel(float* __restrict__ out, int N)
{
    int gid = blockIdx.x * blockDim.x + threadIdx.x;
    int n = gid >> 4;
    if (n >= N) return;
    int part = gid & 15;

    int c = g_cnt[n];
    if (c > CAP) c = CAP;

    const int2* bk = g_bucket + ((size_t)n << 6);
    const float4* p4 = reinterpret_cast<const float4*>(g_proj);

    float4 acc = make_float4(0.f, 0.f, 0.f, 0.f);

    // 1-deep software pipeline: overlap next bucket entry with current gather.
    int2 pr = (c > 0) ? bk[0] : make_int2(0, 0);
    for (int i = 0; i < c; i++) {
        int2 nxt = (i + 1 < c) ? bk[i + 1] : pr;
        float we = __int_as_float(pr.y);
        float4 v = p4[(size_t)pr.x * 16 + part];
        acc.x = fmaf(we, v.x, acc.x);
        acc.y = fmaf(we, v.y, acc.y);
        acc.z = fmaf(we, v.z, acc.z);
        acc.w = fmaf(we, v.w, acc.w);
        pr = nxt;
    }

    reinterpret_cast<float4*>(out)[(size_t)n * 16 + part] = acc;
}

// ---------------------------------------------------------------------------
// Kernel 4: overflow cleanup (normally 0 iterations). Atomic-adds overflow
// edges on top of gather's stored rows.
// ---------------------------------------------------------------------------
__global__ __launch_bounds__(256)
void cleanup_kernel(const int* __restrict__ src, const int* __restrict__ dst,
                    const float* __restrict__ w, float* __restrict__ out)
{
    int m = g_ovf_cnt;
    if (m > OVF_CAP) m = OVF_CAP;
    int total = m * 16;
    const float4* p4 = reinterpret_cast<const float4*>(g_proj);
    for (int idx = blockIdx.x * blockDim.x + threadIdx.x; idx < total;
         idx += gridDim.x * blockDim.x) {
        int e = g_ovf_list[idx >> 4];
        int part = idx & 15;
        int s = src[e], d = dst[e];
        float we = w[e];
        float4 v = p4[(size_t)s * 16 + part];
        float x = we * v.x, y = we * v.y, z = we * v.z, ww = we * v.w;
        asm volatile("red.global.add.v4.f32 [%0], {%1, %2, %3, %4};"
                     :: "l"(out + (size_t)d * 64 + part * 4),
                        "f"(x), "f"(y), "f"(z), "f"(ww)
                     : "memory");
    }
}

// ---------------------------------------------------------------------------
// kernel_launch — graph-capturable, allocation-free.
// Stream fork: GEMM (data,theta -> proj) runs on s1 concurrently with
// memset(cnt)+fill (dst -> buckets) on the main stream; join before gather.
// Input order: src[E] i32, dst[E] i32, w[E] f32, data[N*64] f32,
//              theta[64*64] f32, num_nodes i32
// ---------------------------------------------------------------------------
extern "C" void kernel_launch(void* const* d_in, const int* in_sizes, int n_in,
                              void* d_out, int out_size)
{
    const int*   src   = (const int*)  d_in[0];
    const int*   dst   = (const int*)  d_in[1];
    const float* w     = (const float*)d_in[2];
    const float* data  = (const float*)d_in[3];
    const float* theta = (const float*)d_in[4];

    const int E = in_sizes[0];
    const int N = in_sizes[3] / D;

    float* out = (float*)d_out;

    static float* proj_ptr = nullptr;
    static int*   cnt_ptr  = nullptr;
    static int*   ovf_ptr  = nullptr;
    static cudaStream_t s1 = nullptr;
    static cudaEvent_t evFork = nullptr, evJoin = nullptr;
    if (!proj_ptr) {
        void* p = nullptr;
        cudaGetSymbolAddress(&p, g_proj);    proj_ptr = (float*)p;
        cudaGetSymbolAddress(&p, g_cnt);     cnt_ptr  = (int*)p;
        cudaGetSymbolAddress(&p, g_ovf_cnt); ovf_ptr  = (int*)p;
        cudaStreamCreateWithFlags(&s1, cudaStreamNonBlocking);
        cudaEventCreateWithFlags(&evFork, cudaEventDisableTiming);
        cudaEventCreateWithFlags(&evJoin, cudaEventDisableTiming);
    }

    // Fork: GEMM on s1 (independent of the edge arrays).
    cudaEventRecord(evFork, 0);
    cudaStreamWaitEvent(s1, evFork, 0);
    int gemmBlocks = (N + 63) / 64;
    proj_kernel<<<gemmBlocks, 256, 0, s1>>>(data, theta, proj_ptr, N);
    cudaEventRecord(evJoin, s1);

    // Main stream: reset counters, build buckets.
    cudaMemsetAsync(cnt_ptr, 0, (size_t)MAX_NODES * sizeof(int), 0);
    cudaMemsetAsync(ovf_ptr, 0, sizeof(int), 0);
    int fillBlocks = (E + 255) / 256;
    fill_kernel<<<fillBlocks, 256>>>(src, dst, w, E);

    // Join, then gather-reduce and (trivial) overflow cleanup.
    cudaStreamWaitEvent(0, evJoin, 0);
    long long gthreads = (long long)N * 16;
    int gatherBlocks = (int)((gthreads + 255) / 256);
    gather_kernel<<<gatherBlocks, 256>>>(out, N);
    cleanup_kernel<<<32, 256>>>(src, dst, w, out);
}

// round 14
// speedup vs baseline: 1.3913x; 1.1011x over previous
#include <cuda_runtime.h>
#include <cuda_fp16.h>
#include <cuda_bf16.h>
#include <stdint.h>

// GCN: out[n,:] = sum_{e: dst[e]==n} w[e] * data[src[e],:] @ theta
// project-first (proj = data@theta), bucket-build, per-node gather-reduce.
// R13: fp16 proj (halves gather read stream), FFMA2 (f32x2) GEMM mainloop,
// cleanup kernel folded into gather (never-taken overflow branch).
//
// Shapes (fixed): N = 100000, E = 1200000, D = 64.

#define D 64
#define MAX_NODES 100096
#define CAP 64            // per-node bucket capacity; Poisson(12) max-deg ~40
#define OVF_CAP 32768     // overflow safety net (normally empty)

// Static device scratch (no runtime allocation).
__device__ __half g_projh[(size_t)MAX_NODES * D];        // 12.8 MB (L2-resident)
__device__ int2   g_bucket[(size_t)MAX_NODES * CAP];     // {src, w_bits}
__device__ int    g_cnt[MAX_NODES + 1];                  // [MAX_NODES] = ovf count
__device__ int    g_ovf_list[OVF_CAP];

// ---- packed f32x2 helpers (Blackwell FFMA2; only reachable via PTX) -------
__device__ __forceinline__ unsigned long long pk2(float lo, float hi) {
    unsigned long long r;
    asm("mov.b64 %0, {%1, %2};" : "=l"(r) : "f"(lo), "f"(hi));
    return r;
}
__device__ __forceinline__ void upk2(float& lo, float& hi, unsigned long long v) {
    asm("mov.b64 {%0, %1}, %2;" : "=f"(lo), "=f"(hi) : "l"(v));
}
__device__ __forceinline__ void ffma2(unsigned long long& acc,
                                      unsigned long long a,
                                      unsigned long long b) {
    asm("fma.rn.f32x2 %0, %1, %2, %0;" : "+l"(acc) : "l"(a), "l"(b));
}

// ---------------------------------------------------------------------------
// Kernel 1: proj[N,64] = fp16( data[N,64] @ theta[64,64] )
// 256 threads, 64x64 tile, 4x4 register tile per thread, f32x2 packed FMA.
// ---------------------------------------------------------------------------
__global__ __launch_bounds__(256)
void proj_kernel(const float* __restrict__ data,
                 const float* __restrict__ theta,
                 __half* __restrict__ proj,
                 int N)
{
    __shared__ float sTheta[D * D];   // [k][c]
    __shared__ float sData[64 * D];   // [r][k]

    const int tid = threadIdx.x;
    const int rowBase = blockIdx.x * 64;

    {
        const float4* t4 = reinterpret_cast<const float4*>(theta);
        float4* st4 = reinterpret_cast<float4*>(sTheta);
        #pragma unroll
        for (int i = 0; i < 4; i++)
            st4[tid + i * 256] = t4[tid + i * 256];
    }
    {
        float4* sd4 = reinterpret_cast<float4*>(sData);
        const float4* g4 = reinterpret_cast<const float4*>(data);
        #pragma unroll
        for (int i = 0; i < 4; i++) {
            int idx = tid + i * 256;
            int r = idx >> 4;
            int gr = rowBase + r;
            float4 v = make_float4(0.f, 0.f, 0.f, 0.f);
            if (gr < N) v = g4[(size_t)gr * (D / 4) + (idx & 15)];
            sd4[idx] = v;
        }
    }
    __syncthreads();

    const int ty = tid >> 4;   // rows ty*4..+3
    const int tx = tid & 15;   // cols tx*4..+3 (2 packed col-pairs)

    unsigned long long acc2[4][2];
    #pragma unroll
    for (int i = 0; i < 4; i++) { acc2[i][0] = 0ull; acc2[i][1] = 0ull; }

    #pragma unroll 8
    for (int k = 0; k < D; k++) {
        // two packed column pairs of theta row k
        const unsigned long long* bt =
            reinterpret_cast<const unsigned long long*>(&sTheta[k * D + tx * 4]);
        unsigned long long b01 = bt[0];
        unsigned long long b23 = bt[1];
        #pragma unroll
        for (int i = 0; i < 4; i++) {
            float a = sData[(ty * 4 + i) * D + k];
            unsigned long long aa = pk2(a, a);
            ffma2(acc2[i][0], aa, b01);
            ffma2(acc2[i][1], aa, b23);
        }
    }

    #pragma unroll
    for (int i = 0; i < 4; i++) {
        int gr = rowBase + ty * 4 + i;
        if (gr < N) {
            float c0, c1, c2, c3;
            upk2(c0, c1, acc2[i][0]);
            upk2(c2, c3, acc2[i][1]);
            __half2 h01 = __floats2half2_rn(c0, c1);
            __half2 h23 = __floats2half2_rn(c2, c3);
            uint2 pkd;
            pkd.x = *reinterpret_cast<unsigned*>(&h01);
            pkd.y = *reinterpret_cast<unsigned*>(&h23);
            *reinterpret_cast<uint2*>(&proj[(size_t)gr * D + tx * 4]) = pkd;
        }
    }
}

// ---------------------------------------------------------------------------
// Kernel 2: bucket build (1.2M scalar atomics, then scattered 8B store).
// ---------------------------------------------------------------------------
__global__ __launch_bounds__(256)
void fill_kernel(const int* __restrict__ src, const int* __restrict__ dst,
                 const float* __restrict__ w, int E)
{
    int e = blockIdx.x * blockDim.x + threadIdx.x;
    if (e >= E) return;
    int d = dst[e];
    int pos = atomicAdd(&g_cnt[d], 1);
    if (pos < CAP) {
        g_bucket[((size_t)d << 6) + pos] = make_int2(src[e], __float_as_int(w[e]));
    } else {
        int op = atomicAdd(&g_cnt[MAX_NODES], 1);
        if (op < OVF_CAP) g_ovf_list[op] = e;
    }
}

// ---------------------------------------------------------------------------
// Kernel 3: gather-reduce. 16 lanes/node; lane `part` owns 4 output columns.
// fp16 proj row = 128B, 8B per lane per edge (coalesced across the 16 lanes).
// 2-deep unroll, dual accumulators, one float4 store per lane. Overflow
// (cnt>CAP, ~impossible) handled inline by scanning the overflow list.
// ---------------------------------------------------------------------------
__global__ __launch_bounds__(256)
void gather_kernel(const int* __restrict__ src, const int* __restrict__ dst,
                   const float* __restrict__ w, float* __restrict__ out, int N)
{
    int gid = blockIdx.x * blockDim.x + threadIdx.x;
    int n = gid >> 4;
    if (n >= N) return;
    int part = gid & 15;

    int craw = g_cnt[n];
    int c = craw > CAP ? CAP : craw;

    const int2* bk = g_bucket + ((size_t)n << 6);
    const uint2* p2 = reinterpret_cast<const uint2*>(g_projh);

    float4 acc0 = make_float4(0.f, 0.f, 0.f, 0.f);
    float4 acc1 = make_float4(0.f, 0.f, 0.f, 0.f);

    int i = 0;
    for (; i + 2 <= c; i += 2) {
        int2 e0 = bk[i];
        int2 e1 = bk[i + 1];
        uint2 v0 = p2[(size_t)e0.x * 16 + part];
        uint2 v1 = p2[(size_t)e1.x * 16 + part];
        float w0 = __int_as_float(e0.y);
        float w1 = __int_as_float(e1.y);

        float2 f0a = __half22float2(*reinterpret_cast<__half2*>(&v0.x));
        float2 f0b = __half22float2(*reinterpret_cast<__half2*>(&v0.y));
        acc0.x = fmaf(w0, f0a.x, acc0.x);
        acc0.y = fmaf(w0, f0a.y, acc0.y);
        acc0.z = fmaf(w0, f0b.x, acc0.z);
        acc0.w = fmaf(w0, f0b.y, acc0.w);

        float2 f1a = __half22float2(*reinterpret_cast<__half2*>(&v1.x));
        float2 f1b = __half22float2(*reinterpret_cast<__half2*>(&v1.y));
        acc1.x = fmaf(w1, f1a.x, acc1.x);
        acc1.y = fmaf(w1, f1a.y, acc1.y);
        acc1.z = fmaf(w1, f1b.x, acc1.z);
        acc1.w = fmaf(w1, f1b.y, acc1.w);
    }
    if (i < c) {
        int2 e0 = bk[i];
        uint2 v0 = p2[(size_t)e0.x * 16 + part];
        float w0 = __int_as_float(e0.y);
        float2 f0a = __half22float2(*reinterpret_cast<__half2*>(&v0.x));
        float2 f0b = __half22float2(*reinterpret_cast<__half2*>(&v0.y));
        acc0.x = fmaf(w0, f0a.x, acc0.x);
        acc0.y = fmaf(w0, f0a.y, acc0.y);
        acc0.z = fmaf(w0, f0b.x, acc0.z);
        acc0.w = fmaf(w0, f0b.y, acc0.w);
    }

    // Overflow path: never taken for this dataset (Poisson(12) degrees),
    // but keeps correctness unconditional.
    if (craw > CAP) {
        int m = g_cnt[MAX_NODES];
        if (m > OVF_CAP) m = OVF_CAP;
        for (int j = 0; j < m; j++) {
            int e = g_ovf_list[j];
            if (dst[e] == n) {
                float we = w[e];
                uint2 v = p2[(size_t)src[e] * 16 + part];
                float2 fa = __half22float2(*reinterpret_cast<__half2*>(&v.x));
                float2 fb = __half22float2(*reinterpret_cast<__half2*>(&v.y));
                acc0.x = fmaf(we, fa.x, acc0.x);
                acc0.y = fmaf(we, fa.y, acc0.y);
                acc0.z = fmaf(we, fb.x, acc0.z);
                acc0.w = fmaf(we, fb.y, acc0.w);
            }
        }
    }

    float4 r = make_float4(acc0.x + acc1.x, acc0.y + acc1.y,
                           acc0.z + acc1.z, acc0.w + acc1.w);
    reinterpret_cast<float4*>(out)[(size_t)n * 16 + part] = r;
}

// ---------------------------------------------------------------------------
// kernel_launch — graph-capturable, allocation-free.
// Fork: GEMM on s1 concurrent with memset(cnt)+fill on the main stream.
// Input order: src[E] i32, dst[E] i32, w[E] f32, data[N*64] f32,
//              theta[64*64] f32, num_nodes i32
// ---------------------------------------------------------------------------
extern "C" void kernel_launch(void* const* d_in, const int* in_sizes, int n_in,
                              void* d_out, int out_size)
{
    const int*   src   = (const int*)  d_in[0];
    const int*   dst   = (const int*)  d_in[1];
    const float* w     = (const float*)d_in[2];
    const float* data  = (const float*)d_in[3];
    const float* theta = (const float*)d_in[4];

    const int E = in_sizes[0];
    const int N = in_sizes[3] / D;

    float* out = (float*)d_out;

    static __half* proj_ptr = nullptr;
    static int*    cnt_ptr  = nullptr;
    static cudaStream_t s1 = nullptr;
    static cudaEvent_t evFork = nullptr, evJoin = nullptr;
    if (!proj_ptr) {
        void* p = nullptr;
        cudaGetSymbolAddress(&p, g_projh); proj_ptr = (__half*)p;
        cudaGetSymbolAddress(&p, g_cnt);   cnt_ptr  = (int*)p;
        cudaStreamCreateWithFlags(&s1, cudaStreamNonBlocking);
        cudaEventCreateWithFlags(&evFork, cudaEventDisableTiming);
        cudaEventCreateWithFlags(&evJoin, cudaEventDisableTiming);
    }

    // Fork: GEMM on s1 (independent of the edge arrays).
    cudaEventRecord(evFork, 0);
    cudaStreamWaitEvent(s1, evFork, 0);
    int gemmBlocks = (N + 63) / 64;
    proj_kernel<<<gemmBlocks, 256, 0, s1>>>(data, theta, proj_ptr, N);
    cudaEventRecord(evJoin, s1);

    // Main stream: reset counters (+ ovf counter), build buckets.
    cudaMemsetAsync(cnt_ptr, 0, (size_t)(MAX_NODES + 1) * sizeof(int), 0);
    int fillBlocks = (E + 255) / 256;
    fill_kernel<<<fillBlocks, 256>>>(src, dst, w, E);

    // Join, then gather-reduce (writes every output row; no out memset).
    cudaStreamWaitEvent(0, evJoin, 0);
    long long gthreads = (long long)N * 16;
    int gatherBlocks = (int)((gthreads + 255) / 256);
    gather_kernel<<<gatherBlocks, 256>>>(src, dst, w, out, N);
}